// round 7
// baseline (speedup 1.0000x reference)
#include <cuda_runtime.h>
#include <math.h>

// Problem constants (B=1)
#define Cc    4      // chunks
#define Hh    8      // heads
#define Ll    1024   // chunk length
#define Dd    64     // head dim
#define Tt    (Cc*Ll)
#define NPAIR 2080   // symmetric (d<=e) pairs: 64*65/2
#define NV    65     // 64 value dims + 1 normalizer column
#define SCALEF 0.125f
#define EPSF   1e-6f

// ---------------- scratch (device globals; no allocation allowed) -----------
__device__ float g_g   [Cc*Hh*Ll];          // per-chunk inclusive cumsum of log_g
__device__ float g_w   [Cc*Hh*Ll];          // exp(g_end - g)
__device__ float g_qd  [Cc*Hh*Ll];          // exp(g)
__device__ float g_gtot[Cc*Hh];             // exp(g_end)
__device__ float g_P   [Cc*Hh*NPAIR*NV];    // per-chunk expanded state contribution
__device__ float g_S   [Cc*Hh*NPAIR*NV];    // prefix states (mult-scaled), S[0]=0
__device__ float g_intra[Tt*Hh*Dd];
__device__ float g_row  [Tt*Hh];
__device__ unsigned char g_pd[NPAIR];
__device__ unsigned char g_pe[NPAIR];

// ---------------- K0: pair index tables --------------------------------------
__global__ void k_pairs() {
    int i = blockIdx.x * blockDim.x + threadIdx.x;
    if (i >= NPAIR) return;
    int d = 0, rem = i;
    while (rem >= (Dd - d)) { rem -= (Dd - d); d++; }
    g_pd[i] = (unsigned char)d;
    g_pe[i] = (unsigned char)(d + rem);
}

// ---------------- K1: gating cumsum + derived weights ------------------------
__global__ void k_gate(const float* __restrict__ logg) {
    int ch = blockIdx.x;           // c*Hh + h
    int c = ch / Hh, h = ch % Hh;
    int l = threadIdx.x;
    __shared__ float sbuf[Ll];
    int t = c * Ll + l;
    sbuf[l] = logg[t * Hh + h];
    __syncthreads();
    // Hillis-Steele inclusive scan
    for (int off = 1; off < Ll; off <<= 1) {
        float v   = sbuf[l];
        float add = (l >= off) ? sbuf[l - off] : 0.f;
        __syncthreads();
        sbuf[l] = v + add;
        __syncthreads();
    }
    float g    = sbuf[l];
    float gend = sbuf[Ll - 1];
    int idx = ch * Ll + l;
    g_g [idx] = g;
    g_w [idx] = expf(gend - g);
    g_qd[idx] = expf(g);
    if (l == 0) g_gtot[ch] = expf(gend);
}

// ---------------- K2: intra-chunk causal attention ---------------------------
// grid (8 query tiles, H, C), 128 threads, 1 thread = 1 query row
__global__ void __launch_bounds__(128)
k_intra(const float* __restrict__ q, const float* __restrict__ k,
        const float* __restrict__ v) {
    int tl = 7 - blockIdx.x;            // bigger tiles first
    int h = blockIdx.y, c = blockIdx.z;
    int lrow  = tl * 128 + threadIdx.x; // local row within chunk
    int tglob = c * Ll + lrow;

    float qreg[Dd];
#pragma unroll
    for (int d = 0; d < Dd; d++)
        qreg[d] = q[(tglob * Hh + h) * Dd + d] * SCALEF;
    float gl = g_g[(c * Hh + h) * Ll + lrow];

    float acc[Dd];
#pragma unroll
    for (int d = 0; d < Dd; d++) acc[d] = 0.f;
    float rowsum = 0.f;

    __shared__ __align__(16) float Ks[64][68];
    __shared__ __align__(16) float Vs[64][68];
    __shared__ float Gs[64];

    int ntile = (tl + 1) * 2;           // s-tiles of 64 keys
    for (int st = 0; st < ntile; st++) {
        int sbase = st * 64;
        __syncthreads();
        for (int idx = threadIdx.x; idx < 64 * Dd; idx += 128) {
            int r = idx >> 6, col = idx & 63;
            int ts = c * Ll + sbase + r;
            Ks[r][col] = k[(ts * Hh + h) * Dd + col];
            Vs[r][col] = v[(ts * Hh + h) * Dd + col];
        }
        if (threadIdx.x < 64)
            Gs[threadIdx.x] = g_g[(c * Hh + h) * Ll + sbase + threadIdx.x];
        __syncthreads();

        int smax = lrow - sbase + 1;
        if (smax > 64) smax = 64;
        for (int s = 0; s < smax; s++) {
            const float4* Kr = reinterpret_cast<const float4*>(&Ks[s][0]);
            float s0 = 0.f, s1 = 0.f, s2 = 0.f, s3 = 0.f;
#pragma unroll
            for (int d4 = 0; d4 < 16; d4++) {
                float4 kk = Kr[d4];
                s0 += qreg[4 * d4 + 0] * kk.x;
                s1 += qreg[4 * d4 + 1] * kk.y;
                s2 += qreg[4 * d4 + 2] * kk.z;
                s3 += qreg[4 * d4 + 3] * kk.w;
            }
            float sc = (s0 + s1) + (s2 + s3);
            float a  = expf(gl - Gs[s]) * sc * sc;
            rowsum += a;
            const float4* Vr = reinterpret_cast<const float4*>(&Vs[s][0]);
#pragma unroll
            for (int d4 = 0; d4 < 16; d4++) {
                float4 vv = Vr[d4];
                acc[4 * d4 + 0] += a * vv.x;
                acc[4 * d4 + 1] += a * vv.y;
                acc[4 * d4 + 2] += a * vv.z;
                acc[4 * d4 + 3] += a * vv.w;
            }
        }
    }
    int ohid = tglob * Hh + h;
#pragma unroll
    for (int d = 0; d < Dd; d++) g_intra[ohid * Dd + d] = acc[d];
    g_row[ohid] = rowsum;
}

// ---------------- K3: per-chunk state build P[i,v], Z folded at v=64 ---------
// grid (17 pair tiles, H, C), 128 threads, 1 thread = 1 (d<=e) pair
__global__ void __launch_bounds__(128)
k_state(const float* __restrict__ k, const float* __restrict__ v) {
    int i = blockIdx.x * 128 + threadIdx.x;
    int h = blockIdx.y, c = blockIdx.z;
    bool active = (i < NPAIR);
    int d = 0, e = 0;
    if (active) { d = g_pd[i]; e = g_pe[i]; }

    float acc[Dd];
#pragma unroll
    for (int x = 0; x < Dd; x++) acc[x] = 0.f;
    float accZ = 0.f;

    __shared__ __align__(16) float Ks[32][68];
    __shared__ __align__(16) float Vs[32][68];
    __shared__ float Ws[32];

    for (int lb = 0; lb < Ll; lb += 32) {
        __syncthreads();
        for (int idx = threadIdx.x; idx < 32 * Dd; idx += 128) {
            int r = idx >> 6, col = idx & 63;
            int ts = c * Ll + lb + r;
            Ks[r][col] = k[(ts * Hh + h) * Dd + col];
            Vs[r][col] = v[(ts * Hh + h) * Dd + col];
        }
        if (threadIdx.x < 32)
            Ws[threadIdx.x] = g_w[(c * Hh + h) * Ll + lb + threadIdx.x];
        __syncthreads();

        for (int r = 0; r < 32; r++) {
            float f = Ws[r] * Ks[r][d] * Ks[r][e];
            accZ += f;
            const float4* Vr = reinterpret_cast<const float4*>(&Vs[r][0]);
#pragma unroll
            for (int x4 = 0; x4 < 16; x4++) {
                float4 vv = Vr[x4];
                acc[4 * x4 + 0] += f * vv.x;
                acc[4 * x4 + 1] += f * vv.y;
                acc[4 * x4 + 2] += f * vv.z;
                acc[4 * x4 + 3] += f * vv.w;
            }
        }
    }
    if (active) {
        int base = ((c * Hh + h) * NPAIR + i) * NV;
#pragma unroll
        for (int x = 0; x < Dd; x++) g_P[base + x] = acc[x];
        g_P[base + Dd] = accZ;
    }
}

// ---------------- K4: prefix scan over chunks, fold symmetry multiplicity ----
__global__ void k_scan() {
    int idx = blockIdx.x * blockDim.x + threadIdx.x;
    const int per_h = NPAIR * NV;
    const int tot = Hh * per_h;
    if (idx >= tot) return;
    int h = idx / per_h;
    int rem = idx % per_h;
    int i = rem / NV;
    float mult = (g_pd[i] == g_pe[i]) ? 1.f : 2.f;
    float s = 0.f;
    for (int c = 0; c < Cc; c++) {
        int off = (c * Hh + h) * per_h + rem;
        g_S[off] = mult * s;                       // state BEFORE chunk c
        s = g_gtot[c * Hh + h] * s + g_P[off];     // carry
    }
}

// ---------------- K5: inter-chunk GEMM + final combine ------------------------
// grid (8 row tiles, H, C), 128 threads, 1 thread = 1 query row
__global__ void __launch_bounds__(128)
k_inter(const float* __restrict__ q, float* __restrict__ out) {
    int tl = blockIdx.x;
    int h = blockIdx.y, c = blockIdx.z;
    int lrow  = tl * 128 + threadIdx.x;
    int tglob = c * Ll + lrow;

    __shared__ float Qs[128][65];                 // stride 65 -> conflict-free
    __shared__ __align__(16) float Ss[32][68];
    __shared__ unsigned char Pd[32], Pe[32];

    for (int idx = threadIdx.x; idx < 128 * Dd; idx += 128) {
        int r = idx >> 6, col = idx & 63;
        int tg = c * Ll + tl * 128 + r;
        Qs[r][col] = q[(tg * Hh + h) * Dd + col] * SCALEF;
    }
    __syncthreads();

    float acc[NV + 3];
#pragma unroll
    for (int x = 0; x < NV + 3; x++) acc[x] = 0.f;

    if (c > 0) {
        int Sbase = (c * Hh + h) * NPAIR * NV;
        for (int ib = 0; ib < NPAIR; ib += 32) {
            __syncthreads();
            for (int idx = threadIdx.x; idx < 32 * NV; idx += 128)
                Ss[idx / NV][idx % NV] = g_S[Sbase + ib * NV + idx];
            if (threadIdx.x < 32) {
                Pd[threadIdx.x] = g_pd[ib + threadIdx.x];
                Pe[threadIdx.x] = g_pe[ib + threadIdx.x];
            }
            __syncthreads();
#pragma unroll 4
            for (int ii = 0; ii < 32; ii++) {
                float f = Qs[threadIdx.x][Pd[ii]] * Qs[threadIdx.x][Pe[ii]];
                const float4* Sr = reinterpret_cast<const float4*>(&Ss[ii][0]);
#pragma unroll
                for (int x4 = 0; x4 < 16; x4++) {
                    float4 sv = Sr[x4];
                    acc[4 * x4 + 0] += f * sv.x;
                    acc[4 * x4 + 1] += f * sv.y;
                    acc[4 * x4 + 2] += f * sv.z;
                    acc[4 * x4 + 3] += f * sv.w;
                }
                acc[64] += f * Ss[ii][64];
            }
        }
    }

    float qdec = g_qd[(c * Hh + h) * Ll + lrow];
    int ohid = tglob * Hh + h;
    float den = g_row[ohid] + qdec * acc[64];
    den = fmaxf(den, EPSF);
    float inv = 1.f / den;
#pragma unroll
    for (int x = 0; x < Dd; x++)
        out[ohid * Dd + x] = (g_intra[ohid * Dd + x] + qdec * acc[x]) * inv;
}

// ---------------- host launch -------------------------------------------------
extern "C" void kernel_launch(void* const* d_in, const int* in_sizes, int n_in,
                              void* d_out, int out_size) {
    const float* q  = (const float*)d_in[0];
    const float* k  = (const float*)d_in[1];
    const float* v  = (const float*)d_in[2];
    const float* lg = (const float*)d_in[3];
    float* out = (float*)d_out;

    k_pairs<<<(NPAIR + 127) / 128, 128>>>();
    k_gate <<<Cc * Hh, Ll>>>(lg);
    k_intra<<<dim3(8, Hh, Cc), 128>>>(q, k, v);
    k_state<<<dim3((NPAIR + 127) / 128, Hh, Cc), 128>>>(k, v);
    k_scan <<<(Hh * NPAIR * NV + 255) / 256, 256>>>();
    k_inter<<<dim3(8, Hh, Cc), 128>>>(q, out);
}